// round 4
// baseline (speedup 1.0000x reference)
#include <cuda_runtime.h>
#include <cuda_bf16.h>
#include <math.h>
#include <stdint.h>

#define NB 4
#define SEQL 2048
#define DMODEL 512
#define NHEAD 8
#define HDIM 64
#define WINDOW 256
#define MTOT (NB*SEQL)   // 8192

// Scratch (device globals; no allocation allowed)
__device__ __align__(16) float g_Q[MTOT*DMODEL];     // [B,L,H*d] fp32
__device__ __align__(16) float g_K[MTOT*DMODEL];
__device__ __align__(16) float g_V[MTOT*DMODEL];
__device__ __align__(16) float g_pre[MTOT*DMODEL];   // pre-LayerNorm
__device__ __align__(16) __nv_bfloat16 g_Wh[4*DMODEL*DMODEL];  // W^T hi, [w][n][k]
__device__ __align__(16) __nv_bfloat16 g_Wl[4*DMODEL*DMODEL];  // W^T lo
__device__ __align__(16) __nv_bfloat16 g_Xh[3*MTOT*DMODEL];    // inputs hi
__device__ __align__(16) __nv_bfloat16 g_Xl[3*MTOT*DMODEL];    // inputs lo
__device__ __align__(16) __nv_bfloat16 g_Ch[MTOT*DMODEL];      // ctx hi
__device__ __align__(16) __nv_bfloat16 g_Cl[MTOT*DMODEL];      // ctx lo

// ---------------------------------------------------------------------------
// Generic-PTX helpers (NO tcgen05 — harness compiles for compute_103)
// ---------------------------------------------------------------------------
__device__ __forceinline__ uint32_t smem_u32(const void* p) {
    uint32_t a;
    asm("{ .reg .u64 t; cvta.to.shared.u64 t, %1; cvt.u32.u64 %0, t; }"
        : "=r"(a) : "l"(p));
    return a;
}

__device__ __forceinline__ void cpa16(uint32_t dst, const void* src) {
    asm volatile("cp.async.cg.shared.global [%0], [%1], 16;"
                 :: "r"(dst), "l"(src));
}
#define CP_COMMIT() asm volatile("cp.async.commit_group;")
#define CP_WAIT(n)  asm volatile("cp.async.wait_group " #n ";")

__device__ __forceinline__ void ldmx4(uint32_t addr, uint32_t* r) {
    asm volatile("ldmatrix.sync.aligned.m8n8.x4.shared.b16 {%0,%1,%2,%3}, [%4];"
                 : "=r"(r[0]), "=r"(r[1]), "=r"(r[2]), "=r"(r[3]) : "r"(addr));
}

__device__ __forceinline__ void mma16816(float* d, const uint32_t* a, const uint32_t* b) {
    asm volatile("mma.sync.aligned.m16n8k16.row.col.f32.bf16.bf16.f32 "
                 "{%0,%1,%2,%3}, {%4,%5,%6,%7}, {%8,%9}, {%0,%1,%2,%3};"
                 : "+f"(d[0]), "+f"(d[1]), "+f"(d[2]), "+f"(d[3])
                 : "r"(a[0]), "r"(a[1]), "r"(a[2]), "r"(a[3]),
                   "r"(b[0]), "r"(b[1]));
}

// ---------------------------------------------------------------------------
// Prep: transpose + bf16-split weights: W[k][n] -> Wt_hi/lo[n][k]
// ---------------------------------------------------------------------------
__global__ __launch_bounds__(256)
void prep_w_kernel(const float* __restrict__ w0, const float* __restrict__ w1,
                   const float* __restrict__ w2, const float* __restrict__ w3)
{
    __shared__ float s[32][33];
    const int wsel = blockIdx.z;
    const float* W = (wsel == 0) ? w0 : (wsel == 1) ? w1 : (wsel == 2) ? w2 : w3;
    const int k0 = blockIdx.x * 32, n0 = blockIdx.y * 32;
    const int tx = threadIdx.x, ty = threadIdx.y;

    #pragma unroll
    for (int i = 0; i < 4; i++)
        s[ty + 8 * i][tx] = W[(size_t)(k0 + ty + 8 * i) * DMODEL + n0 + tx];
    __syncthreads();

    const size_t base = (size_t)wsel * DMODEL * DMODEL;
    #pragma unroll
    for (int i = 0; i < 4; i++) {
        int n = n0 + ty + 8 * i, k = k0 + tx;
        float x = s[tx][ty + 8 * i];
        __nv_bfloat16 h = __float2bfloat16(x);
        float lo = x - __bfloat162float(h);
        g_Wh[base + (size_t)n * DMODEL + k] = h;
        g_Wl[base + (size_t)n * DMODEL + k] = __float2bfloat16(lo);
    }
}

// ---------------------------------------------------------------------------
// Prep: split inputs fp32 -> bf16 hi/lo (3 matrices, [8192,512])
// ---------------------------------------------------------------------------
__global__ __launch_bounds__(256)
void prep_x_kernel(const float* __restrict__ x0, const float* __restrict__ x1,
                   const float* __restrict__ x2)
{
    const int sel = blockIdx.y;
    const float* x = (sel == 0) ? x0 : (sel == 1) ? x1 : x2;
    size_t i4 = ((size_t)blockIdx.x * 256 + threadIdx.x);
    float4 v = ((const float4*)x)[i4];
    __nv_bfloat16 h0 = __float2bfloat16(v.x), h1 = __float2bfloat16(v.y);
    __nv_bfloat16 h2 = __float2bfloat16(v.z), h3 = __float2bfloat16(v.w);
    __nv_bfloat16 l0 = __float2bfloat16(v.x - __bfloat162float(h0));
    __nv_bfloat16 l1 = __float2bfloat16(v.y - __bfloat162float(h1));
    __nv_bfloat16 l2 = __float2bfloat16(v.z - __bfloat162float(h2));
    __nv_bfloat16 l3 = __float2bfloat16(v.w - __bfloat162float(h3));
    uint2 uh, ul;
    uh.x = ((uint32_t)__bfloat16_as_ushort(h1) << 16) | __bfloat16_as_ushort(h0);
    uh.y = ((uint32_t)__bfloat16_as_ushort(h3) << 16) | __bfloat16_as_ushort(h2);
    ul.x = ((uint32_t)__bfloat16_as_ushort(l1) << 16) | __bfloat16_as_ushort(l0);
    ul.y = ((uint32_t)__bfloat16_as_ushort(l3) << 16) | __bfloat16_as_ushort(l2);
    const size_t base = (size_t)sel * MTOT * DMODEL;
    ((uint2*)(g_Xh + base))[i4] = uh;
    ((uint2*)(g_Xl + base))[i4] = ul;
}

// ---------------------------------------------------------------------------
// Tensor-core GEMM via mma.sync (bf16, 3-term split, fp32 accum):
// C[8192,512] = A @ W.  Block 128x128, BK=64, 8 warps, warp tile 64x32,
// cp.async double-buffered, XOR-swizzled smem + ldmatrix.
// MODE 0: store C; MODE 1: store C + resid.
// ---------------------------------------------------------------------------
#define STG_BYTES 65536
#define AH_OFF 0
#define AL_OFF 16384
#define BH_OFF 32768
#define BL_OFF 49152

__device__ __forceinline__ void stage_load(uint32_t sbase,
                                           const __nv_bfloat16* __restrict__ g,
                                           int row0, int k0, int tid)
{
    #pragma unroll
    for (int i = 0; i < 4; i++) {
        int idx = tid + i * 256;
        int r = idx >> 3, c = idx & 7;
        const void* src = g + (size_t)(row0 + r) * DMODEL + k0 + c * 8;
        uint32_t dst = sbase + (uint32_t)r * 128 + (uint32_t)((c ^ (r & 7)) << 4);
        cpa16(dst, src);
    }
}

template<int MODE>
__global__ __launch_bounds__(256)
void gemm_tc(const __nv_bfloat16* __restrict__ Ah, const __nv_bfloat16* __restrict__ Al,
             const __nv_bfloat16* __restrict__ Bh, const __nv_bfloat16* __restrict__ Bl,
             const float* __restrict__ resid, float* __restrict__ out)
{
    extern __shared__ char dyn[];
    const uint32_t sb = smem_u32(dyn);
    const int tid  = threadIdx.x;
    const int wid  = tid >> 5, lane = tid & 31;
    const int wm   = wid & 1, wn = wid >> 1;          // 2 x 4 warp grid
    const int bx   = blockIdx.x, by = blockIdx.y;
    const int arow = by * 128, brow = bx * 128;

    float d[4][4][4];
    #pragma unroll
    for (int mi = 0; mi < 4; mi++)
        #pragma unroll
        for (int ni = 0; ni < 4; ni++)
            #pragma unroll
            for (int q = 0; q < 4; q++) d[mi][ni][q] = 0.0f;

    // prologue: stage 0
    stage_load(sb + AH_OFF, Ah, arow, 0, tid);
    stage_load(sb + AL_OFF, Al, arow, 0, tid);
    stage_load(sb + BH_OFF, Bh, brow, 0, tid);
    stage_load(sb + BL_OFF, Bl, brow, 0, tid);
    CP_COMMIT();

    const int g8 = lane >> 3, r8 = lane & 7;

    for (int c = 0; c < 8; c++) {
        if (c < 7) {
            uint32_t s2 = sb + (uint32_t)((c + 1) & 1) * STG_BYTES;
            int k0 = (c + 1) * 64;
            stage_load(s2 + AH_OFF, Ah, arow, k0, tid);
            stage_load(s2 + AL_OFF, Al, arow, k0, tid);
            stage_load(s2 + BH_OFF, Bh, brow, k0, tid);
            stage_load(s2 + BL_OFF, Bl, brow, k0, tid);
            CP_COMMIT();
            CP_WAIT(1);
        } else {
            CP_WAIT(0);
        }
        __syncthreads();

        const uint32_t ss = sb + (uint32_t)(c & 1) * STG_BYTES;
        #pragma unroll
        for (int k16 = 0; k16 < 4; k16++) {
            uint32_t ah[4][4], al[4][4], bh[8], bl[8];
            // A frags: 4 m16 tiles; lane addr: row=m0+r8+(g8&1)*8, chunk=k16*2+(g8>>1)
            #pragma unroll
            for (int mi = 0; mi < 4; mi++) {
                int row = wm * 64 + mi * 16 + r8 + (g8 & 1) * 8;
                int ch  = k16 * 2 + (g8 >> 1);
                uint32_t off = (uint32_t)row * 128 + (uint32_t)((ch ^ (row & 7)) << 4);
                ldmx4(ss + AH_OFF + off, ah[mi]);
                ldmx4(ss + AL_OFF + off, al[mi]);
            }
            // B frags: 2x (pair of n8 tiles); row=n0+r8+(g8>>1)*8, chunk=k16*2+(g8&1)
            #pragma unroll
            for (int np = 0; np < 2; np++) {
                int row = wn * 32 + np * 16 + r8 + (g8 >> 1) * 8;
                int ch  = k16 * 2 + (g8 & 1);
                uint32_t off = (uint32_t)row * 128 + (uint32_t)((ch ^ (row & 7)) << 4);
                ldmx4(ss + BH_OFF + off, &bh[np * 4]);
                ldmx4(ss + BL_OFF + off, &bl[np * 4]);
            }
            #pragma unroll
            for (int mi = 0; mi < 4; mi++)
                #pragma unroll
                for (int ni = 0; ni < 4; ni++) {
                    mma16816(d[mi][ni], ah[mi], &bh[ni * 2]);
                    mma16816(d[mi][ni], al[mi], &bh[ni * 2]);
                    mma16816(d[mi][ni], ah[mi], &bl[ni * 2]);
                }
        }
        __syncthreads();
    }

    // epilogue: d0,d1 -> (row, col..col+1); d2,d3 -> (row+8, ...)
    const int rbase = by * 128 + wm * 64 + (lane >> 2);
    const int cbase = bx * 128 + wn * 32 + (lane & 3) * 2;
    #pragma unroll
    for (int mi = 0; mi < 4; mi++) {
        #pragma unroll
        for (int ni = 0; ni < 4; ni++) {
            int col = cbase + ni * 8;
            #pragma unroll
            for (int half = 0; half < 2; half++) {
                int row = rbase + mi * 16 + half * 8;
                float2 v = make_float2(d[mi][ni][half * 2], d[mi][ni][half * 2 + 1]);
                if (MODE == 1) {
                    float2 rv = *(const float2*)(resid + (size_t)row * DMODEL + col);
                    v.x += rv.x; v.y += rv.y;
                }
                *(float2*)(out + (size_t)row * DMODEL + col) = v;
            }
        }
    }
}

// ---------------------------------------------------------------------------
// Banded flash attention (fp32, proven R1 math; [B,L,H*d] layout).
// Epilogue writes ctx as bf16 hi/lo directly.
// ---------------------------------------------------------------------------
__global__ __launch_bounds__(256)
void attn_kernel()
{
    extern __shared__ float sm[];
    float (*sQt)[68] = (float(*)[68])(sm);
    float (*sKt)[68] = (float(*)[68])(sm + 64 * 68);
    float (*sV )[68] = (float(*)[68])(sm + 2 * 64 * 68);
    float (*sPt)[68] = (float(*)[68])(sm + 3 * 64 * 68);

    const int tid = threadIdx.x;
    const int tx  = tid & 15;
    const int ty  = tid >> 4;
    const int qt  = blockIdx.x;
    const int hh  = blockIdx.y;
    const int b   = blockIdx.z;

    const size_t base = (size_t)b * SEQL * DMODEL + hh * HDIM;
    const float* Qg = g_Q + base;
    const float* Kg = g_K + base;
    const float* Vg = g_V + base;
    const int q0 = qt * 64;

    #pragma unroll
    for (int r = 0; r < 4; r++) {
        int f   = tid + r * 256;
        int row = f >> 4;
        int c4  = (f & 15) << 2;
        float4 v = *(const float4*)(Qg + (size_t)(q0 + row) * DMODEL + c4);
        sQt[c4 + 0][row] = v.x;
        sQt[c4 + 1][row] = v.y;
        sQt[c4 + 2][row] = v.z;
        sQt[c4 + 3][row] = v.w;
    }

    float m_run[4], l_run[4], o[4][4];
    #pragma unroll
    for (int i = 0; i < 4; i++) {
        m_run[i] = -1e30f;
        l_run[i] = 0.0f;
        #pragma unroll
        for (int j = 0; j < 4; j++) o[i][j] = 0.0f;
    }

    const int kt_lo = (qt >= 4) ? (qt - 4) : 0;
    for (int kt = kt_lo; kt <= qt; kt++) {
        __syncthreads();
        const int k0 = kt * 64;
        #pragma unroll
        for (int r = 0; r < 4; r++) {
            int f   = tid + r * 256;
            int row = f >> 4;
            int c4  = (f & 15) << 2;
            float4 kv = *(const float4*)(Kg + (size_t)(k0 + row) * DMODEL + c4);
            sKt[c4 + 0][row] = kv.x;
            sKt[c4 + 1][row] = kv.y;
            sKt[c4 + 2][row] = kv.z;
            sKt[c4 + 3][row] = kv.w;
            *(float4*)&sV[row][c4] =
                *(const float4*)(Vg + (size_t)(k0 + row) * DMODEL + c4);
        }
        __syncthreads();

        float s[4][4];
        #pragma unroll
        for (int i = 0; i < 4; i++)
            #pragma unroll
            for (int j = 0; j < 4; j++) s[i][j] = 0.0f;

        #pragma unroll 8
        for (int kk = 0; kk < 64; kk++) {
            float4 aq = *(float4*)&sQt[kk][ty * 4];
            float4 bk = *(float4*)&sKt[kk][tx * 4];
            float av[4] = {aq.x, aq.y, aq.z, aq.w};
            float bv[4] = {bk.x, bk.y, bk.z, bk.w};
            #pragma unroll
            for (int i = 0; i < 4; i++)
                #pragma unroll
                for (int j = 0; j < 4; j++)
                    s[i][j] = fmaf(av[i], bv[j], s[i][j]);
        }

        #pragma unroll
        for (int i = 0; i < 4; i++) {
            int qi = q0 + ty * 4 + i;
            #pragma unroll
            for (int j = 0; j < 4; j++) {
                int kj = k0 + tx * 4 + j;
                bool valid = (kj <= qi) && (kj >= qi - (WINDOW - 1));
                s[i][j] = valid ? s[i][j] * 0.125f : -INFINITY;
            }
        }

        #pragma unroll
        for (int i = 0; i < 4; i++) {
            float mt = fmaxf(fmaxf(s[i][0], s[i][1]), fmaxf(s[i][2], s[i][3]));
            #pragma unroll
            for (int off = 8; off > 0; off >>= 1)
                mt = fmaxf(mt, __shfl_xor_sync(0xffffffffu, mt, off));
            float m_new = fmaxf(m_run[i], mt);
            float sc    = expf(m_run[i] - m_new);
            float ls    = 0.0f;
            #pragma unroll
            for (int j = 0; j < 4; j++) {
                float p = expf(s[i][j] - m_new);
                s[i][j] = p;
                ls += p;
            }
            #pragma unroll
            for (int off = 8; off > 0; off >>= 1)
                ls += __shfl_xor_sync(0xffffffffu, ls, off);
            l_run[i] = l_run[i] * sc + ls;
            m_run[i] = m_new;
            #pragma unroll
            for (int j = 0; j < 4; j++) o[i][j] *= sc;
        }

        #pragma unroll
        for (int j = 0; j < 4; j++)
            #pragma unroll
            for (int i = 0; i < 4; i++)
                sPt[tx * 4 + j][ty * 4 + i] = s[i][j];
        __syncthreads();

        #pragma unroll 8
        for (int kk = 0; kk < 64; kk++) {
            float4 ap = *(float4*)&sPt[kk][ty * 4];
            float4 vv = *(float4*)&sV[kk][tx * 4];
            float av[4] = {ap.x, ap.y, ap.z, ap.w};
            float bv[4] = {vv.x, vv.y, vv.z, vv.w};
            #pragma unroll
            for (int i = 0; i < 4; i++)
                #pragma unroll
                for (int j = 0; j < 4; j++)
                    o[i][j] = fmaf(av[i], bv[j], o[i][j]);
        }
    }

    // write context [B*L, H*dv] as bf16 hi/lo (ready for out-proj GEMM)
    #pragma unroll
    for (int i = 0; i < 4; i++) {
        float il = 1.0f / l_run[i];
        int q = q0 + ty * 4 + i;
        float vv[4] = {o[i][0] * il, o[i][1] * il, o[i][2] * il, o[i][3] * il};
        __nv_bfloat16 h0 = __float2bfloat16(vv[0]), h1 = __float2bfloat16(vv[1]);
        __nv_bfloat16 h2 = __float2bfloat16(vv[2]), h3 = __float2bfloat16(vv[3]);
        __nv_bfloat16 l0 = __float2bfloat16(vv[0] - __bfloat162float(h0));
        __nv_bfloat16 l1 = __float2bfloat16(vv[1] - __bfloat162float(h1));
        __nv_bfloat16 l2 = __float2bfloat16(vv[2] - __bfloat162float(h2));
        __nv_bfloat16 l3 = __float2bfloat16(vv[3] - __bfloat162float(h3));
        uint2 uh, ul;
        uh.x = ((uint32_t)__bfloat16_as_ushort(h1) << 16) | __bfloat16_as_ushort(h0);
        uh.y = ((uint32_t)__bfloat16_as_ushort(h3) << 16) | __bfloat16_as_ushort(h2);
        ul.x = ((uint32_t)__bfloat16_as_ushort(l1) << 16) | __bfloat16_as_ushort(l0);
        ul.y = ((uint32_t)__bfloat16_as_ushort(l3) << 16) | __bfloat16_as_ushort(l2);
        size_t off = ((size_t)b * SEQL + q) * DMODEL + hh * HDIM + tx * 4;
        *(uint2*)(g_Ch + off) = uh;
        *(uint2*)(g_Cl + off) = ul;
    }
}

// ---------------------------------------------------------------------------
// LayerNorm over last dim (512), one block per row.
// ---------------------------------------------------------------------------
__global__ __launch_bounds__(256)
void ln_kernel(const float* __restrict__ pre, float* __restrict__ out)
{
    __shared__ float red[16];
    const int row = blockIdx.x;
    const int tid = threadIdx.x;
    const float* x = pre + (size_t)row * DMODEL;

    float v0 = x[tid];
    float v1 = x[tid + 256];
    float s  = v0 + v1;
    float sq = v0 * v0 + v1 * v1;

    #pragma unroll
    for (int off = 16; off > 0; off >>= 1) {
        s  += __shfl_xor_sync(0xffffffffu, s, off);
        sq += __shfl_xor_sync(0xffffffffu, sq, off);
    }
    if ((tid & 31) == 0) {
        red[tid >> 5]       = s;
        red[8 + (tid >> 5)] = sq;
    }
    __syncthreads();
    float st = 0.0f, sqt = 0.0f;
    #pragma unroll
    for (int w = 0; w < 8; w++) { st += red[w]; sqt += red[8 + w]; }

    float mean = st * (1.0f / DMODEL);
    float var  = sqt * (1.0f / DMODEL) - mean * mean;
    float rstd = rsqrtf(var + 1e-5f);

    out[(size_t)row * DMODEL + tid]       = (v0 - mean) * rstd;
    out[(size_t)row * DMODEL + tid + 256] = (v1 - mean) * rstd;
}

// ---------------------------------------------------------------------------
extern "C" void kernel_launch(void* const* d_in, const int* in_sizes, int n_in,
                              void* d_out, int out_size)
{
    const float* iQ = (const float*)d_in[0];
    const float* iK = (const float*)d_in[1];
    const float* iV = (const float*)d_in[2];
    const float* wQ = (const float*)d_in[3];
    const float* wK = (const float*)d_in[4];
    const float* wV = (const float*)d_in[5];
    const float* wF = (const float*)d_in[6];
    float* out = (float*)d_out;

    float *pQ, *pK, *pV, *pPre;
    __nv_bfloat16 *pWh, *pWl, *pXh, *pXl, *pCh, *pCl;
    cudaGetSymbolAddress((void**)&pQ,   g_Q);
    cudaGetSymbolAddress((void**)&pK,   g_K);
    cudaGetSymbolAddress((void**)&pV,   g_V);
    cudaGetSymbolAddress((void**)&pPre, g_pre);
    cudaGetSymbolAddress((void**)&pWh,  g_Wh);
    cudaGetSymbolAddress((void**)&pWl,  g_Wl);
    cudaGetSymbolAddress((void**)&pXh,  g_Xh);
    cudaGetSymbolAddress((void**)&pXl,  g_Xl);
    cudaGetSymbolAddress((void**)&pCh,  g_Ch);
    cudaGetSymbolAddress((void**)&pCl,  g_Cl);

    // Prep
    prep_w_kernel<<<dim3(16, 16, 4), dim3(32, 8)>>>(wQ, wK, wV, wF);
    prep_x_kernel<<<dim3(MTOT * DMODEL / 4 / 256, 3), 256>>>(iQ, iK, iV);

    // Tensor-core GEMMs
    const int gemm_smem = 2 * STG_BYTES;   // 131072
    cudaFuncSetAttribute((const void*)gemm_tc<0>,
                         cudaFuncAttributeMaxDynamicSharedMemorySize, gemm_smem);
    cudaFuncSetAttribute((const void*)gemm_tc<1>,
                         cudaFuncAttributeMaxDynamicSharedMemorySize, gemm_smem);

    const size_t WSZ = (size_t)DMODEL * DMODEL;
    const size_t XSZ = (size_t)MTOT * DMODEL;
    dim3 gg(DMODEL / 128, MTOT / 128);   // (4, 64)
    gemm_tc<0><<<gg, 256, gemm_smem>>>(pXh + 0 * XSZ, pXl + 0 * XSZ,
                                       pWh + 0 * WSZ, pWl + 0 * WSZ, nullptr, pQ);
    gemm_tc<0><<<gg, 256, gemm_smem>>>(pXh + 1 * XSZ, pXl + 1 * XSZ,
                                       pWh + 1 * WSZ, pWl + 1 * WSZ, nullptr, pK);
    gemm_tc<0><<<gg, 256, gemm_smem>>>(pXh + 2 * XSZ, pXl + 2 * XSZ,
                                       pWh + 2 * WSZ, pWl + 2 * WSZ, nullptr, pV);

    // Attention
    int attn_smem = 4 * 64 * 68 * (int)sizeof(float);
    cudaFuncSetAttribute((const void*)attn_kernel,
                         cudaFuncAttributeMaxDynamicSharedMemorySize, attn_smem);
    dim3 ga(SEQL / 64, NHEAD, NB);
    attn_kernel<<<ga, 256, attn_smem>>>();

    // Output projection + residual
    gemm_tc<1><<<gg, 256, gemm_smem>>>(pCh, pCl,
                                       pWh + 3 * WSZ, pWl + 3 * WSZ, iQ, pPre);

    ln_kernel<<<MTOT, 256>>>(pPre, out);
}

// round 5
// speedup vs baseline: 1.5327x; 1.5327x over previous
#include <cuda_runtime.h>
#include <cuda_bf16.h>
#include <math.h>
#include <stdint.h>

#define NB 4
#define SEQL 2048
#define DMODEL 512
#define NHEAD 8
#define HDIM 64
#define WINDOW 256
#define MTOT (NB*SEQL)
#define XSZ ((size_t)MTOT*DMODEL)
#define WSZ ((size_t)DMODEL*DMODEL)

__device__ __align__(16) float g_pre[MTOT*DMODEL];
__device__ __align__(16) __nv_bfloat16 g_Wh[4*DMODEL*DMODEL];
__device__ __align__(16) __nv_bfloat16 g_Wl[4*DMODEL*DMODEL];
__device__ __align__(16) __nv_bfloat16 g_Xh[3*MTOT*DMODEL];
__device__ __align__(16) __nv_bfloat16 g_Xl[3*MTOT*DMODEL];
__device__ __align__(16) __nv_bfloat16 g_QKVh[3*MTOT*DMODEL];  // [sel][B*L][512]
__device__ __align__(16) __nv_bfloat16 g_QKVl[3*MTOT*DMODEL];
__device__ __align__(16) __nv_bfloat16 g_Ch[MTOT*DMODEL];
__device__ __align__(16) __nv_bfloat16 g_Cl[MTOT*DMODEL];

__device__ __forceinline__ uint32_t smem_u32(const void* p) {
    uint32_t a;
    asm("{ .reg .u64 t; cvta.to.shared.u64 t, %1; cvt.u32.u64 %0, t; }" : "=r"(a) : "l"(p));
    return a;
}
__device__ __forceinline__ void cpa16(uint32_t dst, const void* src) {
    asm volatile("cp.async.cg.shared.global [%0], [%1], 16;" :: "r"(dst), "l"(src));
}
#define CP_COMMIT() asm volatile("cp.async.commit_group;")
#define CP_WAIT(n)  asm volatile("cp.async.wait_group " #n ";")
__device__ __forceinline__ void ldmx4(uint32_t a, uint32_t* r) {
    asm volatile("ldmatrix.sync.aligned.m8n8.x4.shared.b16 {%0,%1,%2,%3}, [%4];"
                 : "=r"(r[0]), "=r"(r[1]), "=r"(r[2]), "=r"(r[3]) : "r"(a));
}
__device__ __forceinline__ void ldmx4t(uint32_t a, uint32_t* r) {
    asm volatile("ldmatrix.sync.aligned.m8n8.x4.trans.shared.b16 {%0,%1,%2,%3}, [%4];"
                 : "=r"(r[0]), "=r"(r[1]), "=r"(r[2]), "=r"(r[3]) : "r"(a));
}
__device__ __forceinline__ void mma16816(float* d, const uint32_t* a, const uint32_t* b) {
    asm volatile("mma.sync.aligned.m16n8k16.row.col.f32.bf16.bf16.f32 "
                 "{%0,%1,%2,%3}, {%4,%5,%6,%7}, {%8,%9}, {%0,%1,%2,%3};"
                 : "+f"(d[0]), "+f"(d[1]), "+f"(d[2]), "+f"(d[3])
                 : "r"(a[0]), "r"(a[1]), "r"(a[2]), "r"(a[3]), "r"(b[0]), "r"(b[1]));
}
__device__ __forceinline__ uint32_t packbf(float v0, float v1) {
    uint32_t r;
    asm("cvt.rn.bf16x2.f32 %0, %1, %2;" : "=r"(r) : "f"(v1), "f"(v0));
    return r;
}
__device__ __forceinline__ void split2(float v0, float v1, uint32_t& h, uint32_t& l) {
    h = packbf(v0, v1);
    l = packbf(v0 - __uint_as_float(h << 16), v1 - __uint_as_float(h & 0xFFFF0000u));
}

// ---- prep: W^T hi/lo (scale 0.125 folded into W_Q) -------------------------
__global__ __launch_bounds__(256)
void prep_w_kernel(const float* __restrict__ w0, const float* __restrict__ w1,
                   const float* __restrict__ w2, const float* __restrict__ w3)
{
    __shared__ float s[32][33];
    const int wsel = blockIdx.z;
    const float* W = (wsel == 0) ? w0 : (wsel == 1) ? w1 : (wsel == 2) ? w2 : w3;
    const float scale = (wsel == 0) ? 0.125f : 1.0f;
    const int k0 = blockIdx.x * 32, n0 = blockIdx.y * 32;
    const int tx = threadIdx.x, ty = threadIdx.y;
    #pragma unroll
    for (int i = 0; i < 4; i++)
        s[ty + 8 * i][tx] = W[(size_t)(k0 + ty + 8 * i) * DMODEL + n0 + tx];
    __syncthreads();
    const size_t base = (size_t)wsel * WSZ;
    #pragma unroll
    for (int i = 0; i < 4; i++) {
        int n = n0 + ty + 8 * i, k = k0 + tx;
        float x = s[tx][ty + 8 * i] * scale;
        __nv_bfloat16 h = __float2bfloat16(x);
        g_Wh[base + (size_t)n * DMODEL + k] = h;
        g_Wl[base + (size_t)n * DMODEL + k] = __float2bfloat16(x - __bfloat162float(h));
    }
}

// ---- prep: inputs fp32 -> bf16 hi/lo ---------------------------------------
__global__ __launch_bounds__(256)
void prep_x_kernel(const float* __restrict__ x0, const float* __restrict__ x1,
                   const float* __restrict__ x2)
{
    const int sel = blockIdx.y;
    const float* x = (sel == 0) ? x0 : (sel == 1) ? x1 : x2;
    size_t i4 = (size_t)blockIdx.x * 256 + threadIdx.x;
    float4 v = ((const float4*)x)[i4];
    uint32_t h0, l0, h1, l1;
    split2(v.x, v.y, h0, l0);
    split2(v.z, v.w, h1, l1);
    const size_t base = (size_t)sel * XSZ;
    ((uint2*)(g_Xh + base))[i4] = make_uint2(h0, h1);
    ((uint2*)(g_Xl + base))[i4] = make_uint2(l0, l1);
}

// ---- tensor-core GEMM (proven R3 mainloop) ----------------------------------
// MODE 0: fused QKV (wsel = blockIdx.z), out bf16 hi/lo. MODE 1: fp32 + resid.
#define STG_BYTES 65536
__device__ __forceinline__ void stage_load(uint32_t sbase,
    const __nv_bfloat16* __restrict__ g, int row0, int k0, int tid)
{
    #pragma unroll
    for (int i = 0; i < 4; i++) {
        int idx = tid + i * 256;
        int r = idx >> 3, c = idx & 7;
        cpa16(sbase + (uint32_t)r * 128 + (uint32_t)((c ^ (r & 7)) << 4),
              g + (size_t)(row0 + r) * DMODEL + k0 + c * 8);
    }
}

template<int MODE>
__global__ __launch_bounds__(256)
void gemm_tc(const __nv_bfloat16* __restrict__ Ah_, const __nv_bfloat16* __restrict__ Al_,
             const __nv_bfloat16* __restrict__ Wh_, const __nv_bfloat16* __restrict__ Wl_,
             const float* __restrict__ resid, float* __restrict__ outF,
             __nv_bfloat16* __restrict__ outH, __nv_bfloat16* __restrict__ outL)
{
    extern __shared__ char dyn[];
    const uint32_t sb = smem_u32(dyn);
    const int tid = threadIdx.x, wid = tid >> 5, lane = tid & 31;
    const int wm = wid & 1, wn = wid >> 1;
    const int bx = blockIdx.x, by = blockIdx.y;
    const int wsel = (MODE == 0) ? (int)blockIdx.z : 0;
    const __nv_bfloat16* Ah = Ah_ + (size_t)wsel * XSZ;
    const __nv_bfloat16* Al = Al_ + (size_t)wsel * XSZ;
    const __nv_bfloat16* Bh = Wh_ + (size_t)wsel * WSZ;
    const __nv_bfloat16* Bl = Wl_ + (size_t)wsel * WSZ;
    const int arow = by * 128, brow = bx * 128;

    float d[4][4][4];
    #pragma unroll
    for (int mi = 0; mi < 4; mi++)
        #pragma unroll
        for (int ni = 0; ni < 4; ni++)
            #pragma unroll
            for (int q = 0; q < 4; q++) d[mi][ni][q] = 0.0f;

    stage_load(sb +     0, Ah, arow, 0, tid);
    stage_load(sb + 16384, Al, arow, 0, tid);
    stage_load(sb + 32768, Bh, brow, 0, tid);
    stage_load(sb + 49152, Bl, brow, 0, tid);
    CP_COMMIT();

    const int g8 = lane >> 3, r8 = lane & 7;
    for (int c = 0; c < 8; c++) {
        if (c < 7) {
            uint32_t s2 = sb + (uint32_t)((c + 1) & 1) * STG_BYTES;
            int k0 = (c + 1) * 64;
            stage_load(s2 +     0, Ah, arow, k0, tid);
            stage_load(s2 + 16384, Al, arow, k0, tid);
            stage_load(s2 + 32768, Bh, brow, k0, tid);
            stage_load(s2 + 49152, Bl, brow, k0, tid);
            CP_COMMIT(); CP_WAIT(1);
        } else { CP_WAIT(0); }
        __syncthreads();

        const uint32_t ss = sb + (uint32_t)(c & 1) * STG_BYTES;
        #pragma unroll
        for (int k16 = 0; k16 < 4; k16++) {
            uint32_t ah[4][4], al[4][4], bh[8], bl[8];
            #pragma unroll
            for (int mi = 0; mi < 4; mi++) {
                int row = wm * 64 + mi * 16 + r8 + (g8 & 1) * 8;
                int ch  = k16 * 2 + (g8 >> 1);
                uint32_t off = (uint32_t)row * 128 + (uint32_t)((ch ^ (row & 7)) << 4);
                ldmx4(ss + off, ah[mi]);
                ldmx4(ss + 16384 + off, al[mi]);
            }
            #pragma unroll
            for (int np = 0; np < 2; np++) {
                int row = wn * 32 + np * 16 + r8 + (g8 >> 1) * 8;
                int ch  = k16 * 2 + (g8 & 1);
                uint32_t off = (uint32_t)row * 128 + (uint32_t)((ch ^ (row & 7)) << 4);
                ldmx4(ss + 32768 + off, &bh[np * 4]);
                ldmx4(ss + 49152 + off, &bl[np * 4]);
            }
            #pragma unroll
            for (int mi = 0; mi < 4; mi++)
                #pragma unroll
                for (int ni = 0; ni < 4; ni++) {
                    mma16816(d[mi][ni], ah[mi], &bh[ni * 2]);
                    mma16816(d[mi][ni], al[mi], &bh[ni * 2]);
                    mma16816(d[mi][ni], ah[mi], &bl[ni * 2]);
                }
        }
        __syncthreads();
    }

    const int rbase = by * 128 + wm * 64 + (lane >> 2);
    const int cbase = bx * 128 + wn * 32 + (lane & 3) * 2;
    #pragma unroll
    for (int mi = 0; mi < 4; mi++)
        #pragma unroll
        for (int ni = 0; ni < 4; ni++) {
            int col = cbase + ni * 8;
            #pragma unroll
            for (int hf = 0; hf < 2; hf++) {
                int row = rbase + mi * 16 + hf * 8;
                size_t off = (size_t)row * DMODEL + col;
                if (MODE == 0) {
                    uint32_t hh, ll;
                    split2(d[mi][ni][hf * 2], d[mi][ni][hf * 2 + 1], hh, ll);
                    *(uint32_t*)(outH + (size_t)wsel * XSZ + off) = hh;
                    *(uint32_t*)(outL + (size_t)wsel * XSZ + off) = ll;
                } else {
                    float2 rv = *(const float2*)(resid + off);
                    *(float2*)(outF + off) = make_float2(d[mi][ni][hf * 2] + rv.x,
                                                         d[mi][ni][hf * 2 + 1] + rv.y);
                }
            }
        }
}

// ---- tensor-core banded flash attention -------------------------------------
// block = (qtile 64, head, batch), 128 threads (4 warps x m16), d=64.
// smem: Qh 0, Ql 8192; stage s at 16384+s*32768: Kh,Kl,Vh,Vl (8KB each).
__device__ __forceinline__ void stage_kv(uint32_t sb, int s, int b, int h,
                                         int krow0, int tid)
{
    const uint32_t base = sb + 16384u + (uint32_t)s * 32768u;
    #pragma unroll
    for (int i = 0; i < 16; i++) {
        int idx = tid + i * 128;
        int mat = idx >> 9, rem = idx & 511;
        int r = rem >> 3, ch = rem & 7;
        const __nv_bfloat16* src =
            (mat == 0 ? g_QKVh + 1 * XSZ : mat == 1 ? g_QKVl + 1 * XSZ :
             mat == 2 ? g_QKVh + 2 * XSZ : g_QKVl + 2 * XSZ)
            + (size_t)(b * SEQL + krow0 + r) * DMODEL + h * HDIM + ch * 8;
        cpa16(base + (uint32_t)mat * 8192u + (uint32_t)r * 128u
                   + (uint32_t)((ch ^ (r & 7)) << 4), src);
    }
}

__global__ __launch_bounds__(128, 2)
void attn_tc()
{
    extern __shared__ char dyn[];
    const uint32_t sb = smem_u32(dyn);
    const int tid = threadIdx.x, wid = tid >> 5, lane = tid & 31;
    const int r8 = lane & 7, g8 = lane >> 3;
    const int qt = blockIdx.x, h = blockIdx.y, b = blockIdx.z;
    const int q0 = qt * 64;

    #pragma unroll
    for (int i = 0; i < 8; i++) {   // stage Q hi/lo
        int idx = tid + i * 128;
        int mat = idx >> 9, rem = idx & 511;
        int r = rem >> 3, ch = rem & 7;
        const __nv_bfloat16* src = (mat ? g_QKVl : g_QKVh)
            + (size_t)(b * SEQL + q0 + r) * DMODEL + h * HDIM + ch * 8;
        cpa16(sb + (uint32_t)mat * 8192u + (uint32_t)r * 128u
                 + (uint32_t)((ch ^ (r & 7)) << 4), src);
    }
    const int kt_lo = (qt >= 4) ? qt - 4 : 0;
    stage_kv(sb, 0, b, h, kt_lo * 64, tid);
    CP_COMMIT(); CP_WAIT(0);
    __syncthreads();

    uint32_t qh[4][4], ql[4][4];
    #pragma unroll
    for (int k16 = 0; k16 < 4; k16++) {
        int row = wid * 16 + r8 + (g8 & 1) * 8;
        int ch  = k16 * 2 + (g8 >> 1);
        uint32_t off = (uint32_t)row * 128u + (uint32_t)((ch ^ (row & 7)) << 4);
        ldmx4(sb + off, qh[k16]);
        ldmx4(sb + 8192u + off, ql[k16]);
    }

    float o[8][4];
    #pragma unroll
    for (int ni = 0; ni < 8; ni++)
        #pragma unroll
        for (int c = 0; c < 4; c++) o[ni][c] = 0.0f;
    float m_run[2] = {-1e30f, -1e30f}, l_run[2] = {0.0f, 0.0f};

    for (int kt = kt_lo; kt <= qt; kt++) {
        const int s = (kt - kt_lo) & 1;
        if (kt < qt) { stage_kv(sb, s ^ 1, b, h, (kt + 1) * 64, tid); CP_COMMIT(); }
        const uint32_t kb = sb + 16384u + (uint32_t)s * 32768u;

        float sc[8][4];
        #pragma unroll
        for (int ni = 0; ni < 8; ni++)
            #pragma unroll
            for (int c = 0; c < 4; c++) sc[ni][c] = 0.0f;

        #pragma unroll
        for (int k16 = 0; k16 < 4; k16++) {
            uint32_t kh[4][4], kl[4][4];
            #pragma unroll
            for (int ng = 0; ng < 4; ng++) {
                int row = ng * 16 + r8 + (g8 >> 1) * 8;
                int ch  = k16 * 2 + (g8 & 1);
                uint32_t off = (uint32_t)row * 128u + (uint32_t)((ch ^ (row & 7)) << 4);
                ldmx4(kb + off, kh[ng]);
                ldmx4(kb + 8192u + off, kl[ng]);
            }
            #pragma unroll
            for (int ng = 0; ng < 4; ng++)
                #pragma unroll
                for (int hf = 0; hf < 2; hf++) {
                    int ni = ng * 2 + hf;
                    mma16816(sc[ni], qh[k16], &kh[ng][hf * 2]);
                    mma16816(sc[ni], ql[k16], &kh[ng][hf * 2]);
                    mma16816(sc[ni], qh[k16], &kl[ng][hf * 2]);
                }
        }

        const int k0 = kt * 64;
        if (kt == qt || (qt >= 4 && kt == qt - 4)) {
            const bool diag = (kt == qt);
            const int qr0 = q0 + wid * 16 + (lane >> 2);
            #pragma unroll
            for (int ni = 0; ni < 8; ni++) {
                int kj = k0 + ni * 8 + 2 * (lane & 3);
                #pragma unroll
                for (int c = 0; c < 4; c++) {
                    int kcol = kj + (c & 1), qrow = qr0 + (c >> 1) * 8;
                    bool ok = diag ? (kcol <= qrow) : (kcol >= qrow - (WINDOW - 1));
                    if (!ok) sc[ni][c] = -INFINITY;
                }
            }
        }

        float mt0 = -INFINITY, mt1 = -INFINITY;
        #pragma unroll
        for (int ni = 0; ni < 8; ni++) {
            mt0 = fmaxf(mt0, fmaxf(sc[ni][0], sc[ni][1]));
            mt1 = fmaxf(mt1, fmaxf(sc[ni][2], sc[ni][3]));
        }
        #pragma unroll
        for (int off = 1; off <= 2; off <<= 1) {
            mt0 = fmaxf(mt0, __shfl_xor_sync(0xffffffffu, mt0, off));
            mt1 = fmaxf(mt1, __shfl_xor_sync(0xffffffffu, mt1, off));
        }
        float mn0 = fmaxf(m_run[0], mt0), mn1 = fmaxf(m_run[1], mt1);
        float e0 = __expf(m_run[0] - mn0), e1 = __expf(m_run[1] - mn1);
        float sum0 = 0.0f, sum1 = 0.0f;
        #pragma unroll
        for (int ni = 0; ni < 8; ni++) {
            sc[ni][0] = __expf(sc[ni][0] - mn0); sum0 += sc[ni][0];
            sc[ni][1] = __expf(sc[ni][1] - mn0); sum0 += sc[ni][1];
            sc[ni][2] = __expf(sc[ni][2] - mn1); sum1 += sc[ni][2];
            sc[ni][3] = __expf(sc[ni][3] - mn1); sum1 += sc[ni][3];
        }
        #pragma unroll
        for (int off = 1; off <= 2; off <<= 1) {
            sum0 += __shfl_xor_sync(0xffffffffu, sum0, off);
            sum1 += __shfl_xor_sync(0xffffffffu, sum1, off);
        }
        l_run[0] = l_run[0] * e0 + sum0;
        l_run[1] = l_run[1] * e1 + sum1;
        m_run[0] = mn0; m_run[1] = mn1;
        #pragma unroll
        for (int ni = 0; ni < 8; ni++) {
            o[ni][0] *= e0; o[ni][1] *= e0; o[ni][2] *= e1; o[ni][3] *= e1;
        }

        uint32_t ph[4][4], pl[4][4];   // P as A-fragments (hi/lo)
        #pragma unroll
        for (int t = 0; t < 4; t++) {
            split2(sc[2*t][0],   sc[2*t][1],   ph[t][0], pl[t][0]);
            split2(sc[2*t][2],   sc[2*t][3],   ph[t][1], pl[t][1]);
            split2(sc[2*t+1][0], sc[2*t+1][1], ph[t][2], pl[t][2]);
            split2(sc[2*t+1][2], sc[2*t+1][3], ph[t][3], pl[t][3]);
        }

        const uint32_t vb = kb + 16384u;
        #pragma unroll
        for (int kt16 = 0; kt16 < 4; kt16++) {
            uint32_t vh[4][4], vl[4][4];
            #pragma unroll
            for (int ng = 0; ng < 4; ng++) {
                int row = kt16 * 16 + r8 + (g8 & 1) * 8;
                int ch  = ng * 2 + (g8 >> 1);
                uint32_t off = (uint32_t)row * 128u + (uint32_t)((ch ^ (row & 7)) << 4);
                ldmx4t(vb + off, vh[ng]);
                ldmx4t(vb + 8192u + off, vl[ng]);
            }
            #pragma unroll
            for (int ng = 0; ng < 4; ng++)
                #pragma unroll
                for (int hf = 0; hf < 2; hf++) {
                    int ni = ng * 2 + hf;
                    mma16816(o[ni], ph[kt16], &vh[ng][hf * 2]);
                    mma16816(o[ni], pl[kt16], &vh[ng][hf * 2]);
                    mma16816(o[ni], ph[kt16], &vl[ng][hf * 2]);
                }
        }
        if (kt < qt) { CP_WAIT(0); __syncthreads(); }
    }

    const float i0 = 1.0f / l_run[0], i1 = 1.0f / l_run[1];
    const int row0 = q0 + wid * 16 + (lane >> 2);
    #pragma unroll
    for (int ni = 0; ni < 8; ni++) {
        int col = h * HDIM + ni * 8 + 2 * (lane & 3);
        size_t o0 = (size_t)(b * SEQL + row0) * DMODEL + col;
        size_t o1 = o0 + 8 * DMODEL;
        uint32_t hh, ll;
        split2(o[ni][0] * i0, o[ni][1] * i0, hh, ll);
        *(uint32_t*)(g_Ch + o0) = hh; *(uint32_t*)(g_Cl + o0) = ll;
        split2(o[ni][2] * i1, o[ni][3] * i1, hh, ll);
        *(uint32_t*)(g_Ch + o1) = hh; *(uint32_t*)(g_Cl + o1) = ll;
    }
}

// ---- LayerNorm ---------------------------------------------------------------
__global__ __launch_bounds__(256)
void ln_kernel(const float* __restrict__ pre, float* __restrict__ out)
{
    __shared__ float red[16];
    const int row = blockIdx.x, tid = threadIdx.x;
    const float* x = pre + (size_t)row * DMODEL;
    float v0 = x[tid], v1 = x[tid + 256];
    float s = v0 + v1, sq = v0 * v0 + v1 * v1;
    #pragma unroll
    for (int off = 16; off > 0; off >>= 1) {
        s  += __shfl_xor_sync(0xffffffffu, s, off);
        sq += __shfl_xor_sync(0xffffffffu, sq, off);
    }
    if ((tid & 31) == 0) { red[tid >> 5] = s; red[8 + (tid >> 5)] = sq; }
    __syncthreads();
    float st = 0.0f, sqt = 0.0f;
    #pragma unroll
    for (int w = 0; w < 8; w++) { st += red[w]; sqt += red[8 + w]; }
    float mean = st * (1.0f / DMODEL);
    float var  = sqt * (1.0f / DMODEL) - mean * mean;
    float rstd = rsqrtf(var + 1e-5f);
    out[(size_t)row * DMODEL + tid]       = (v0 - mean) * rstd;
    out[(size_t)row * DMODEL + tid + 256] = (v1 - mean) * rstd;
}

// ------------------------------------------------------------------------------
extern "C" void kernel_launch(void* const* d_in, const int* in_sizes, int n_in,
                              void* d_out, int out_size)
{
    const float* iQ = (const float*)d_in[0];
    const float* iK = (const float*)d_in[1];
    const float* iV = (const float*)d_in[2];
    const float* wQ = (const float*)d_in[3];
    const float* wK = (const float*)d_in[4];
    const float* wV = (const float*)d_in[5];
    const float* wF = (const float*)d_in[6];
    float* out = (float*)d_out;

    float* pPre;
    __nv_bfloat16 *pWh, *pWl, *pXh, *pXl, *pQKVh, *pQKVl, *pCh, *pCl;
    cudaGetSymbolAddress((void**)&pPre,  g_pre);
    cudaGetSymbolAddress((void**)&pWh,   g_Wh);
    cudaGetSymbolAddress((void**)&pWl,   g_Wl);
    cudaGetSymbolAddress((void**)&pXh,   g_Xh);
    cudaGetSymbolAddress((void**)&pXl,   g_Xl);
    cudaGetSymbolAddress((void**)&pQKVh, g_QKVh);
    cudaGetSymbolAddress((void**)&pQKVl, g_QKVl);
    cudaGetSymbolAddress((void**)&pCh,   g_Ch);
    cudaGetSymbolAddress((void**)&pCl,   g_Cl);

    prep_w_kernel<<<dim3(16, 16, 4), dim3(32, 8)>>>(wQ, wK, wV, wF);
    prep_x_kernel<<<dim3(MTOT * DMODEL / 4 / 256, 3), 256>>>(iQ, iK, iV);

    const int gemm_smem = 2 * STG_BYTES;
    cudaFuncSetAttribute((const void*)gemm_tc<0>,
                         cudaFuncAttributeMaxDynamicSharedMemorySize, gemm_smem);
    cudaFuncSetAttribute((const void*)gemm_tc<1>,
                         cudaFuncAttributeMaxDynamicSharedMemorySize, gemm_smem);
    cudaFuncSetAttribute((const void*)attn_tc,
                         cudaFuncAttributeMaxDynamicSharedMemorySize, 81920);

    gemm_tc<0><<<dim3(4, 64, 3), 256, gemm_smem>>>(pXh, pXl, pWh, pWl,
                                                   nullptr, nullptr, pQKVh, pQKVl);
    attn_tc<<<dim3(SEQL / 64, NHEAD, NB), 128, 81920>>>();
    gemm_tc<1><<<dim3(4, 64), 256, gemm_smem>>>(pCh, pCl, pWh + 3 * WSZ, pWl + 3 * WSZ,
                                                iQ, pPre, nullptr, nullptr);
    ln_kernel<<<MTOT, 256>>>(pPre, out);
}